// round 10
// baseline (speedup 1.0000x reference)
#include <cuda_runtime.h>

// Problem constants (fixed by the dataset)
#define NN    50000
#define EE    800000
#define FND   8
#define TIN   8
#define HIDN  16
#define TOUTN 4
#define SLOTS 11   // 8 initial time slices + 3 propagated h's
#define ROWF  (SLOTS * FND)   // 88 floats per node row in g_Px

// Scratch (device globals: no allocation allowed)
__device__ int   g_cnt[NN];
__device__ int   g_pos[NN];
__device__ int   g_off[NN];
__device__ int   g_total;
__device__ int   g_csr[EE];              // src list grouped by dst
__device__ float g_dinv[NN];
__device__ float g_nself[NN];
__device__ float g_Px[(size_t)NN * ROWF];   // [n][slot][f], 17.6 MB
__device__ float g_hbuf[(size_t)NN * FND];
__device__ float g_M[3 * 128];           // folded W@L_top per gate (8x16)
__device__ float g_fb[3 * 16];           // folded bias b@L_top + Lb per gate

// ---------------------------------------------------------------------------
__global__ void k_zero_int(int N) {
    int i = blockIdx.x * blockDim.x + threadIdx.x;
    if (i < N) { g_cnt[i] = 0; g_pos[i] = 0; }
    if (i == 0) g_total = 0;
}

__global__ void k_cnt(const int* __restrict__ ei, int E) {
    int i = blockIdx.x * blockDim.x + threadIdx.x;
    if (i < E) atomicAdd(&g_cnt[ei[E + i]], 1);   // dst = ei[E + e]
}

__global__ void k_norm(int N) {
    int i = blockIdx.x * blockDim.x + threadIdx.x;
    if (i < N) {
        float d = (float)g_cnt[i] + 1.0f;
        g_dinv[i]  = rsqrtf(d);
        g_nself[i] = __fdividef(1.0f, d);   // dinv*dinv
    }
}

// Fold the two-layer gate algebra:
//   concat(P@W + b, H) @ L + Lb  ==  P@(W@L_top) + (b@L_top + Lb) + H@L_bot
__global__ void k_fold(const float* __restrict__ Wz, const float* __restrict__ bz,
                       const float* __restrict__ Lzw, const float* __restrict__ Lzb,
                       const float* __restrict__ Wr, const float* __restrict__ br,
                       const float* __restrict__ Lrw, const float* __restrict__ Lrb,
                       const float* __restrict__ Wh, const float* __restrict__ bh,
                       const float* __restrict__ Lhw, const float* __restrict__ Lhb) {
    int t = threadIdx.x;
    if (t >= 48) return;
    int gate = t >> 4;
    int j = t & 15;
    const float *W, *b, *L, *Lb;
    if      (gate == 0) { W = Wz; b = bz; L = Lzw; Lb = Lzb; }
    else if (gate == 1) { W = Wr; b = br; L = Lrw; Lb = Lrb; }
    else                { W = Wh; b = bh; L = Lhw; Lb = Lhb; }
#pragma unroll
    for (int k = 0; k < 8; k++) {
        float m = 0.0f;
#pragma unroll
        for (int i = 0; i < 16; i++) m = fmaf(W[k * 16 + i], L[i * 16 + j], m);
        g_M[gate * 128 + k * 16 + j] = m;
    }
    float fb = Lb[j];
#pragma unroll
    for (int i = 0; i < 16; i++) fb = fmaf(b[i], L[i * 16 + j], fb);
    g_fb[gate * 16 + j] = fb;
}

// Unordered CSR slot allocation: per-block scan + one global atomicAdd.
__global__ void k_alloc(int N) {
    __shared__ int wsum[8];
    __shared__ int sbase;
    int i = blockIdx.x * 256 + threadIdx.x;
    int lane = threadIdx.x & 31;
    int wid  = threadIdx.x >> 5;
    int c = (i < N) ? g_cnt[i] : 0;
    int v = c;
#pragma unroll
    for (int d = 1; d < 32; d <<= 1) {
        int u = __shfl_up_sync(0xffffffffu, v, d);
        if (lane >= d) v += u;
    }
    if (lane == 31) wsum[wid] = v;
    __syncthreads();
    if (threadIdx.x < 8) {
        int w = wsum[threadIdx.x];
#pragma unroll
        for (int d = 1; d < 8; d <<= 1) {
            int u = __shfl_up_sync(0xffu, w, d, 8);
            if (threadIdx.x >= (unsigned)d) w += u;
        }
        wsum[threadIdx.x] = w;
        if (threadIdx.x == 7) sbase = atomicAdd(&g_total, w);
    }
    __syncthreads();
    int excl = v - c + (wid > 0 ? wsum[wid - 1] : 0) + sbase;
    if (i < N) g_off[i] = excl;
}

__global__ void k_scatter(const int* __restrict__ ei, int E) {
    int e = blockIdx.x * blockDim.x + threadIdx.x;
    if (e >= E) return;
    int d = ei[E + e];
    int p = atomicAdd(&g_pos[d], 1);
    g_csr[g_off[d] + p] = ei[e];
}

// Gather-based propagation of all 8 initial slices + self term.
__global__ void k_gather_init(const float* __restrict__ x, int N) {
    int i = blockIdx.x * blockDim.x + threadIdx.x;
    int n = i >> 3;
    int f = i & 7;
    if (n >= N) return;
    float dn = g_dinv[n];
    float ns = g_nself[n];
    const float4* xs = (const float4*)(x + (size_t)n * 64 + f * 8);
    float4 sa = xs[0], sb = xs[1];
    float a0 = ns * sa.x, a1 = ns * sa.y, a2 = ns * sa.z, a3 = ns * sa.w;
    float a4 = ns * sb.x, a5 = ns * sb.y, a6 = ns * sb.z, a7 = ns * sb.w;
    int beg = g_off[n], end = beg + g_cnt[n];
#pragma unroll 4
    for (int j = beg; j < end; j++) {
        int s = g_csr[j];
        float ne = dn * g_dinv[s];
        const float4* xp = (const float4*)(x + (size_t)s * 64 + f * 8);
        float4 u = xp[0], v = xp[1];
        a0 = fmaf(u.x, ne, a0); a1 = fmaf(u.y, ne, a1);
        a2 = fmaf(u.z, ne, a2); a3 = fmaf(u.w, ne, a3);
        a4 = fmaf(v.x, ne, a4); a5 = fmaf(v.y, ne, a5);
        a6 = fmaf(v.z, ne, a6); a7 = fmaf(v.w, ne, a7);
    }
    float* pr = g_Px + (size_t)n * ROWF + f;   // Px[n][t][f] = pr[t*8]
    pr[0]  = a0; pr[8]  = a1; pr[16] = a2; pr[24] = a3;
    pr[32] = a4; pr[40] = a5; pr[48] = a6; pr[56] = a7;
}

// Gather-based propagation of h into one slot (self term pre-stored by scan).
__global__ void k_gather_h(int N, int slot) {
    int i = blockIdx.x * blockDim.x + threadIdx.x;
    int n = i >> 3;
    int f = i & 7;
    if (n >= N) return;
    float dn = g_dinv[n];
    float* pp = g_Px + (size_t)n * ROWF + slot * 8 + f;
    float acc = *pp;
    int beg = g_off[n], end = beg + g_cnt[n];
#pragma unroll 4
    for (int j = beg; j < end; j++) {
        int s = g_csr[j];
        float ne = dn * g_dinv[s];
        acc = fmaf(g_hbuf[(size_t)s * 8 + f], ne, acc);
    }
    *pp = acc;
}

__device__ __forceinline__ float sigmoid_f(float x) {
    return __fdividef(1.0f, 1.0f + __expf(-x));
}
__device__ __forceinline__ float tanh_f(float x) {
    float e = __expf(-2.0f * x);
    return __fdividef(1.0f - e, 1.0f + e);
}

// One 16B weight load feeds FOUR nodes (16 FMAs per LDS.128).
// Accumulators named A##A0..A##D3 (prefix A = z, r, or hc).
#define ROWF4(BASE, ROW, VA, VB, VC, VD, A) do {                          \
    float4 w_ = *(const float4*)((BASE) + (ROW) * 16 + q4);               \
    A##A0 = fmaf((VA), w_.x, A##A0); A##A1 = fmaf((VA), w_.y, A##A1);     \
    A##A2 = fmaf((VA), w_.z, A##A2); A##A3 = fmaf((VA), w_.w, A##A3);     \
    A##B0 = fmaf((VB), w_.x, A##B0); A##B1 = fmaf((VB), w_.y, A##B1);     \
    A##B2 = fmaf((VB), w_.z, A##B2); A##B3 = fmaf((VB), w_.w, A##B3);     \
    A##C0 = fmaf((VC), w_.x, A##C0); A##C1 = fmaf((VC), w_.y, A##C1);     \
    A##C2 = fmaf((VC), w_.z, A##C2); A##C3 = fmaf((VC), w_.w, A##C3);     \
    A##D0 = fmaf((VD), w_.x, A##D0); A##D1 = fmaf((VD), w_.y, A##D1);     \
    A##D2 = fmaf((VD), w_.z, A##D2); A##D3 = fmaf((VD), w_.w, A##D3); } while (0)

// Layer-1 folded: 8 P features through the 8x16 M matrix, four nodes at once
#define DOT8P4(BASE, A) do {                                              \
    ROWF4(BASE, 0, qaA.x, qaB.x, qaC.x, qaD.x, A);                        \
    ROWF4(BASE, 1, qaA.y, qaB.y, qaC.y, qaD.y, A);                        \
    ROWF4(BASE, 2, qaA.z, qaB.z, qaC.z, qaD.z, A);                        \
    ROWF4(BASE, 3, qaA.w, qaB.w, qaC.w, qaD.w, A);                        \
    ROWF4(BASE, 4, qbA.x, qbB.x, qbC.x, qbD.x, A);                        \
    ROWF4(BASE, 5, qbA.y, qbB.y, qbC.y, qbD.y, A);                        \
    ROWF4(BASE, 6, qbA.z, qbB.z, qbC.z, qbD.z, A);                        \
    ROWF4(BASE, 7, qbA.w, qbB.w, qbC.w, qbD.w, A); } while (0)

// Broadcast 8 per-unit values (half of 16) from the 4-lane node group.
// Values i = L*4+j live in sublane L + (j>>2), slot j&3. L = 0 (units 0-7) or 2 (units 8-15).
#define BCAST8(P, S0, S1, S2, S3, L) do {                                 \
    P##0 = __shfl_sync(0xffffffffu, S0, (L), 4);                          \
    P##1 = __shfl_sync(0xffffffffu, S1, (L), 4);                          \
    P##2 = __shfl_sync(0xffffffffu, S2, (L), 4);                          \
    P##3 = __shfl_sync(0xffffffffu, S3, (L), 4);                          \
    P##4 = __shfl_sync(0xffffffffu, S0, (L) + 1, 4);                      \
    P##5 = __shfl_sync(0xffffffffu, S1, (L) + 1, 4);                      \
    P##6 = __shfl_sync(0xffffffffu, S2, (L) + 1, 4);                      \
    P##7 = __shfl_sync(0xffffffffu, S3, (L) + 1, 4); } while (0)

// 8 H rows [ROW0..ROW0+7] of the H-portion matrix, four nodes at once
#define DOT8H4(BASE, ROW0, A) do {                                        \
    ROWF4(BASE, (ROW0) + 0, hpA0, hpB0, hpC0, hpD0, A);                   \
    ROWF4(BASE, (ROW0) + 1, hpA1, hpB1, hpC1, hpD1, A);                   \
    ROWF4(BASE, (ROW0) + 2, hpA2, hpB2, hpC2, hpD2, A);                   \
    ROWF4(BASE, (ROW0) + 3, hpA3, hpB3, hpC3, hpD3, A);                   \
    ROWF4(BASE, (ROW0) + 4, hpA4, hpB4, hpC4, hpD4, A);                   \
    ROWF4(BASE, (ROW0) + 5, hpA5, hpB5, hpC5, hpD5, A);                   \
    ROWF4(BASE, (ROW0) + 6, hpA6, hpB6, hpC6, hpD6, A);                   \
    ROWF4(BASE, (ROW0) + 7, hpA7, hpB7, hpC7, hpD7, A); } while (0)

#define HP_DECL float hpA0, hpA1, hpA2, hpA3, hpA4, hpA5, hpA6, hpA7,     \
                      hpB0, hpB1, hpB2, hpB3, hpB4, hpB5, hpB6, hpB7,     \
                      hpC0, hpC1, hpC2, hpC3, hpC4, hpC5, hpC6, hpC7,     \
                      hpD0, hpD1, hpD2, hpD3, hpD4, hpD5, hpD6, hpD7

// Per-node output projection + stores
#define EPILOGUE(AX0, AX1, AX2, AX3, NODE, VALID) do {                    \
    float r0 = fmaxf(AX0, 0.f), r1 = fmaxf(AX1, 0.f);                     \
    float r2 = fmaxf(AX2, 0.f), r3 = fmaxf(AX3, 0.f);                     \
    float o0 = OUTF(0), o1 = OUTF(1), o2 = OUTF(2), o3 = OUTF(3);         \
    float o4 = OUTF(4), o5 = OUTF(5), o6 = OUTF(6), o7 = OUTF(7);         \
    o0 += __shfl_xor_sync(0xffffffffu, o0, 1, 4);                         \
    o1 += __shfl_xor_sync(0xffffffffu, o1, 1, 4);                         \
    o2 += __shfl_xor_sync(0xffffffffu, o2, 1, 4);                         \
    o3 += __shfl_xor_sync(0xffffffffu, o3, 1, 4);                         \
    o4 += __shfl_xor_sync(0xffffffffu, o4, 1, 4);                         \
    o5 += __shfl_xor_sync(0xffffffffu, o5, 1, 4);                         \
    o6 += __shfl_xor_sync(0xffffffffu, o6, 1, 4);                         \
    o7 += __shfl_xor_sync(0xffffffffu, o7, 1, 4);                         \
    o0 += __shfl_xor_sync(0xffffffffu, o0, 2, 4);                         \
    o1 += __shfl_xor_sync(0xffffffffu, o1, 2, 4);                         \
    o2 += __shfl_xor_sync(0xffffffffu, o2, 2, 4);                         \
    o3 += __shfl_xor_sync(0xffffffffu, o3, 2, 4);                         \
    o4 += __shfl_xor_sync(0xffffffffu, o4, 2, 4);                         \
    o5 += __shfl_xor_sync(0xffffffffu, o5, 2, 4);                         \
    o6 += __shfl_xor_sync(0xffffffffu, o6, 2, 4);                         \
    o7 += __shfl_xor_sync(0xffffffffu, o7, 2, 4);                         \
    o0 += sbo[0]; o1 += sbo[1]; o2 += sbo[2]; o3 += sbo[3];               \
    o4 += sbo[4]; o5 += sbo[5]; o6 += sbo[6]; o7 += sbo[7];               \
    float wa, wb2;                                                        \
    if      (q == 0) { wa = o0; wb2 = o1; }                               \
    else if (q == 1) { wa = o2; wb2 = o3; }                               \
    else if (q == 2) { wa = o4; wb2 = o5; }                               \
    else             { wa = o6; wb2 = o7; }                               \
    if (VALID) {                                                          \
        int f = 2 * q;                                                    \
        float* op = out + (size_t)(NODE) * 32 + o;                        \
        op[f * 4]       = wa;                                             \
        op[(f + 1) * 4] = wb2;                                            \
        if (o < 3) {                                                      \
            float ns = g_nself[(NODE)];                                   \
            float* hbp = g_hbuf + (size_t)(NODE) * 8;                     \
            float* psp = g_Px + (size_t)(NODE) * ROWF + (8 + o) * 8;      \
            hbp[f]     = wa;                                              \
            hbp[f + 1] = wb2;                                             \
            psp[f]     = ns * wa;                                         \
            psp[f + 1] = ns * wb2;                                        \
        }                                                                 \
    }                                                                     \
} while (0)

// Fused 8-step GRU scan for one output iteration o.
// 4 lanes per node, FOUR nodes per lane (block covers 128 nodes).
// gate = sigma(P@M + H@L_bot + fb); H-broadcasts processed in 8-unit halves
// shared between the z and r gates to cap register liveness.
__global__ void __launch_bounds__(128)
k_scan(const float* __restrict__ att,
       const float* __restrict__ Lzw, const float* __restrict__ Lrw,
       const float* __restrict__ Lhw,
       const float* __restrict__ Wout, const float* __restrict__ bout,
       float* __restrict__ out, int N, int o)
{
    __shared__ __align__(16) float sMz[128], sMr[128], sMh[128];
    __shared__ __align__(16) float sLz[256], sLr[256], sLh[256];   // L bottom halves
    __shared__ __align__(16) float sfbz[16], sfbr[16], sfbh[16];
    __shared__ __align__(16) float sWo[128], sbo[8], sp[8];

    int tid = threadIdx.x;
    if (tid < 128) {
        sMz[tid] = g_M[tid]; sMr[tid] = g_M[128 + tid]; sMh[tid] = g_M[256 + tid];
        sWo[tid] = Wout[tid];
    }
    for (int i = tid; i < 256; i += 128) {
        sLz[i] = Lzw[256 + i]; sLr[i] = Lrw[256 + i]; sLh[i] = Lhw[256 + i];
    }
    if (tid < 16) {
        sfbz[tid] = g_fb[tid]; sfbr[tid] = g_fb[16 + tid]; sfbh[tid] = g_fb[32 + tid];
    }
    if (tid < 8) {
        sbo[tid] = bout[tid];
        float v = att[tid];
        float m = v;
        m = fmaxf(m, __shfl_xor_sync(0xffu, m, 1, 8));
        m = fmaxf(m, __shfl_xor_sync(0xffu, m, 2, 8));
        m = fmaxf(m, __shfl_xor_sync(0xffu, m, 4, 8));
        float e = __expf(v - m);
        float s = e;
        s += __shfl_xor_sync(0xffu, s, 1, 8);
        s += __shfl_xor_sync(0xffu, s, 2, 8);
        s += __shfl_xor_sync(0xffu, s, 4, 8);
        sp[tid] = __fdividef(e, s);
    }
    __syncthreads();

    int g = tid >> 2;
    int nodeA = blockIdx.x * 128 + g;
    int nodeB = nodeA + 32;
    int nodeC = nodeA + 64;
    int nodeD = nodeA + 96;
    bool validA = (nodeA < N), validB = (nodeB < N);
    bool validC = (nodeC < N), validD = (nodeD < N);
    if (nodeA >= N) nodeA = N - 1;
    if (nodeB >= N) nodeB = N - 1;
    if (nodeC >= N) nodeC = N - 1;
    if (nodeD >= N) nodeD = N - 1;
    int q  = tid & 3;
    int q4 = q * 4;

    float HA0 = 0.f, HA1 = 0.f, HA2 = 0.f, HA3 = 0.f;
    float HB0 = 0.f, HB1 = 0.f, HB2 = 0.f, HB3 = 0.f;
    float HC0 = 0.f, HC1 = 0.f, HC2 = 0.f, HC3 = 0.f;
    float HD0 = 0.f, HD1 = 0.f, HD2 = 0.f, HD3 = 0.f;
    float AA0 = 0.f, AA1 = 0.f, AA2 = 0.f, AA3 = 0.f;
    float AB0 = 0.f, AB1 = 0.f, AB2 = 0.f, AB3 = 0.f;
    float AC0 = 0.f, AC1 = 0.f, AC2 = 0.f, AC3 = 0.f;
    float AD0 = 0.f, AD1 = 0.f, AD2 = 0.f, AD3 = 0.f;

    const float* prowA = g_Px + (size_t)nodeA * ROWF + o * 8;
    const float* prowB = g_Px + (size_t)nodeB * ROWF + o * 8;
    const float* prowC = g_Px + (size_t)nodeC * ROWF + o * 8;
    const float* prowD = g_Px + (size_t)nodeD * ROWF + o * 8;

#pragma unroll 1
    for (int t = 0; t < 8; t++) {
        float4 qaA = ((const float4*)(prowA + t * 8))[0];
        float4 qbA = ((const float4*)(prowA + t * 8))[1];
        float4 qaB = ((const float4*)(prowB + t * 8))[0];
        float4 qbB = ((const float4*)(prowB + t * 8))[1];
        float4 qaC = ((const float4*)(prowC + t * 8))[0];
        float4 qbC = ((const float4*)(prowC + t * 8))[1];
        float4 qaD = ((const float4*)(prowD + t * 8))[0];
        float4 qbD = ((const float4*)(prowD + t * 8))[1];

        // ---- z and r gate accumulators ----
        float4 bv = *(const float4*)(sfbz + q4);
        float zA0 = bv.x, zA1 = bv.y, zA2 = bv.z, zA3 = bv.w;
        float zB0 = bv.x, zB1 = bv.y, zB2 = bv.z, zB3 = bv.w;
        float zC0 = bv.x, zC1 = bv.y, zC2 = bv.z, zC3 = bv.w;
        float zD0 = bv.x, zD1 = bv.y, zD2 = bv.z, zD3 = bv.w;
        bv = *(const float4*)(sfbr + q4);
        float rA0 = bv.x, rA1 = bv.y, rA2 = bv.z, rA3 = bv.w;
        float rB0 = bv.x, rB1 = bv.y, rB2 = bv.z, rB3 = bv.w;
        float rC0 = bv.x, rC1 = bv.y, rC2 = bv.z, rC3 = bv.w;
        float rD0 = bv.x, rD1 = bv.y, rD2 = bv.z, rD3 = bv.w;

        DOT8P4(sMz, z);
        DOT8P4(sMr, r);

        {   // H units 0-7 shared by z and r
            HP_DECL;
            BCAST8(hpA, HA0, HA1, HA2, HA3, 0);
            BCAST8(hpB, HB0, HB1, HB2, HB3, 0);
            BCAST8(hpC, HC0, HC1, HC2, HC3, 0);
            BCAST8(hpD, HD0, HD1, HD2, HD3, 0);
            DOT8H4(sLz, 0, z);
            DOT8H4(sLr, 0, r);
        }
        {   // H units 8-15 shared by z and r
            HP_DECL;
            BCAST8(hpA, HA0, HA1, HA2, HA3, 2);
            BCAST8(hpB, HB0, HB1, HB2, HB3, 2);
            BCAST8(hpC, HC0, HC1, HC2, HC3, 2);
            BCAST8(hpD, HD0, HD1, HD2, HD3, 2);
            DOT8H4(sLz, 8, z);
            DOT8H4(sLr, 8, r);
        }

        float ZA0 = sigmoid_f(zA0), ZA1 = sigmoid_f(zA1), ZA2 = sigmoid_f(zA2), ZA3 = sigmoid_f(zA3);
        float ZB0 = sigmoid_f(zB0), ZB1 = sigmoid_f(zB1), ZB2 = sigmoid_f(zB2), ZB3 = sigmoid_f(zB3);
        float ZC0 = sigmoid_f(zC0), ZC1 = sigmoid_f(zC1), ZC2 = sigmoid_f(zC2), ZC3 = sigmoid_f(zC3);
        float ZD0 = sigmoid_f(zD0), ZD1 = sigmoid_f(zD1), ZD2 = sigmoid_f(zD2), ZD3 = sigmoid_f(zD3);
        float RA0 = HA0 * sigmoid_f(rA0), RA1 = HA1 * sigmoid_f(rA1);
        float RA2 = HA2 * sigmoid_f(rA2), RA3 = HA3 * sigmoid_f(rA3);
        float RB0 = HB0 * sigmoid_f(rB0), RB1 = HB1 * sigmoid_f(rB1);
        float RB2 = HB2 * sigmoid_f(rB2), RB3 = HB3 * sigmoid_f(rB3);
        float RC0 = HC0 * sigmoid_f(rC0), RC1 = HC1 * sigmoid_f(rC1);
        float RC2 = HC2 * sigmoid_f(rC2), RC3 = HC3 * sigmoid_f(rC3);
        float RD0 = HD0 * sigmoid_f(rD0), RD1 = HD1 * sigmoid_f(rD1);
        float RD2 = HD2 * sigmoid_f(rD2), RD3 = HD3 * sigmoid_f(rD3);

        // ---- h gate ----
        bv = *(const float4*)(sfbh + q4);
        float hA0 = bv.x, hA1 = bv.y, hA2 = bv.z, hA3 = bv.w;
        float hB0 = bv.x, hB1 = bv.y, hB2 = bv.z, hB3 = bv.w;
        float hC0 = bv.x, hC1 = bv.y, hC2 = bv.z, hC3 = bv.w;
        float hD0 = bv.x, hD1 = bv.y, hD2 = bv.z, hD3 = bv.w;
        DOT8P4(sMh, h);
        {   // HR units 0-7
            HP_DECL;
            BCAST8(hpA, RA0, RA1, RA2, RA3, 0);
            BCAST8(hpB, RB0, RB1, RB2, RB3, 0);
            BCAST8(hpC, RC0, RC1, RC2, RC3, 0);
            BCAST8(hpD, RD0, RD1, RD2, RD3, 0);
            DOT8H4(sLh, 0, h);
        }
        {   // HR units 8-15
            HP_DECL;
            BCAST8(hpA, RA0, RA1, RA2, RA3, 2);
            BCAST8(hpB, RB0, RB1, RB2, RB3, 2);
            BCAST8(hpC, RC0, RC1, RC2, RC3, 2);
            BCAST8(hpD, RD0, RD1, RD2, RD3, 2);
            DOT8H4(sLh, 8, h);
        }

        float pt = sp[t];
        HA0 = ZA0 * HA0 + (1.0f - ZA0) * tanh_f(hA0);  AA0 = fmaf(pt, HA0, AA0);
        HA1 = ZA1 * HA1 + (1.0f - ZA1) * tanh_f(hA1);  AA1 = fmaf(pt, HA1, AA1);
        HA2 = ZA2 * HA2 + (1.0f - ZA2) * tanh_f(hA2);  AA2 = fmaf(pt, HA2, AA2);
        HA3 = ZA3 * HA3 + (1.0f - ZA3) * tanh_f(hA3);  AA3 = fmaf(pt, HA3, AA3);
        HB0 = ZB0 * HB0 + (1.0f - ZB0) * tanh_f(hB0);  AB0 = fmaf(pt, HB0, AB0);
        HB1 = ZB1 * HB1 + (1.0f - ZB1) * tanh_f(hB1);  AB1 = fmaf(pt, HB1, AB1);
        HB2 = ZB2 * HB2 + (1.0f - ZB2) * tanh_f(hB2);  AB2 = fmaf(pt, HB2, AB2);
        HB3 = ZB3 * HB3 + (1.0f - ZB3) * tanh_f(hB3);  AB3 = fmaf(pt, HB3, AB3);
        HC0 = ZC0 * HC0 + (1.0f - ZC0) * tanh_f(hC0);  AC0 = fmaf(pt, HC0, AC0);
        HC1 = ZC1 * HC1 + (1.0f - ZC1) * tanh_f(hC1);  AC1 = fmaf(pt, HC1, AC1);
        HC2 = ZC2 * HC2 + (1.0f - ZC2) * tanh_f(hC2);  AC2 = fmaf(pt, HC2, AC2);
        HC3 = ZC3 * HC3 + (1.0f - ZC3) * tanh_f(hC3);  AC3 = fmaf(pt, HC3, AC3);
        HD0 = ZD0 * HD0 + (1.0f - ZD0) * tanh_f(hD0);  AD0 = fmaf(pt, HD0, AD0);
        HD1 = ZD1 * HD1 + (1.0f - ZD1) * tanh_f(hD1);  AD1 = fmaf(pt, HD1, AD1);
        HD2 = ZD2 * HD2 + (1.0f - ZD2) * tanh_f(hD2);  AD2 = fmaf(pt, HD2, AD2);
        HD3 = ZD3 * HD3 + (1.0f - ZD3) * tanh_f(hD3);  AD3 = fmaf(pt, HD3, AD3);
    }

#define OUTF(F) (fmaf(r0, sWo[(q4 + 0) * 8 + (F)],                        \
                 fmaf(r1, sWo[(q4 + 1) * 8 + (F)],                        \
                 fmaf(r2, sWo[(q4 + 2) * 8 + (F)],                        \
                      r3 * sWo[(q4 + 3) * 8 + (F)]))))
    EPILOGUE(AA0, AA1, AA2, AA3, nodeA, validA);
    EPILOGUE(AB0, AB1, AB2, AB3, nodeB, validB);
    EPILOGUE(AC0, AC1, AC2, AC3, nodeC, validC);
    EPILOGUE(AD0, AD1, AD2, AD3, nodeD, validD);
#undef OUTF
}

// ---------------------------------------------------------------------------
extern "C" void kernel_launch(void* const* d_in, const int* in_sizes, int n_in,
                              void* d_out, int out_size)
{
    const float* x    = (const float*)d_in[0];
    const int*   ei   = (const int*)d_in[1];
    const float* att  = (const float*)d_in[2];
    const float* Wz   = (const float*)d_in[3];
    const float* bz   = (const float*)d_in[4];
    const float* Lzw  = (const float*)d_in[5];
    const float* Lzb  = (const float*)d_in[6];
    const float* Wr   = (const float*)d_in[7];
    const float* br   = (const float*)d_in[8];
    const float* Lrw  = (const float*)d_in[9];
    const float* Lrb  = (const float*)d_in[10];
    const float* Wh   = (const float*)d_in[11];
    const float* bh   = (const float*)d_in[12];
    const float* Lhw  = (const float*)d_in[13];
    const float* Lhb  = (const float*)d_in[14];
    const float* Wout = (const float*)d_in[15];
    const float* bout = (const float*)d_in[16];
    float* out = (float*)d_out;

    int N = in_sizes[0] / (FND * TIN);
    int E = in_sizes[1] / 2;
    if (N > NN) N = NN;   // static scratch capacity guard
    if (E > EE) E = EE;

    const int TB = 256;
    // ---- CSR build + weight fold (once per launch) ----
    k_zero_int<<<(N + TB - 1) / TB, TB>>>(N);
    k_cnt<<<(E + TB - 1) / TB, TB>>>(ei, E);
    k_norm<<<(N + TB - 1) / TB, TB>>>(N);
    k_alloc<<<(N + 255) / 256, 256>>>(N);
    k_scatter<<<(E + TB - 1) / TB, TB>>>(ei, E);
    k_fold<<<1, 64>>>(Wz, bz, Lzw, Lzb, Wr, br, Lrw, Lrb, Wh, bh, Lhw, Lhb);
    // ---- initial propagation (gather, no atomics) ----
    {
        long long tot = (long long)N * 8;
        k_gather_init<<<(int)((tot + TB - 1) / TB), TB>>>(x, N);
    }

    for (int o = 0; o < TOUTN; o++) {
        k_scan<<<(N + 127) / 128, 128>>>(att, Lzw, Lrw, Lhw, Wout, bout, out, N, o);
        if (o < 3) {
            long long tot = (long long)N * 8;
            k_gather_h<<<(int)((tot + TB - 1) / TB), TB>>>(N, 8 + o);
        }
    }
}

// round 11
// speedup vs baseline: 1.0948x; 1.0948x over previous
#include <cuda_runtime.h>

// Problem constants (fixed by the dataset)
#define NN    50000
#define EE    800000
#define FND   8
#define TIN   8
#define HIDN  16
#define TOUTN 4
#define SLOTS 11   // 8 initial time slices + 3 propagated h's
#define ROWF  (SLOTS * FND)   // 88 floats per node row in g_Px

// Scratch (device globals: no allocation allowed)
__device__ int   g_cnt[NN];
__device__ int   g_pos[NN];
__device__ int   g_off[NN];
__device__ int   g_total;
__device__ int   g_csr[EE];              // src list grouped by dst
__device__ float g_dinv[NN];
__device__ float g_nself[NN];
__device__ float g_Px[(size_t)NN * ROWF];   // [n][slot][f], 17.6 MB
__device__ float g_hbuf[(size_t)NN * FND];
__device__ float g_M[3 * 128];           // folded W@L_top per gate (8x16)
__device__ float g_fb[3 * 16];           // folded bias b@L_top + Lb per gate

// ---------------------------------------------------------------------------
__global__ void k_zero_int(int N) {
    int i = blockIdx.x * blockDim.x + threadIdx.x;
    if (i < N) { g_cnt[i] = 0; g_pos[i] = 0; }
    if (i == 0) g_total = 0;
}

__global__ void k_cnt(const int* __restrict__ ei, int E) {
    int i = blockIdx.x * blockDim.x + threadIdx.x;
    if (i < E) atomicAdd(&g_cnt[ei[E + i]], 1);   // dst = ei[E + e]
}

__global__ void k_norm(int N) {
    int i = blockIdx.x * blockDim.x + threadIdx.x;
    if (i < N) {
        float d = (float)g_cnt[i] + 1.0f;
        g_dinv[i]  = rsqrtf(d);
        g_nself[i] = __fdividef(1.0f, d);   // dinv*dinv
    }
}

// Fold the two-layer gate algebra:
//   concat(P@W + b, H) @ L + Lb  ==  P@(W@L_top) + (b@L_top + Lb) + H@L_bot
__global__ void k_fold(const float* __restrict__ Wz, const float* __restrict__ bz,
                       const float* __restrict__ Lzw, const float* __restrict__ Lzb,
                       const float* __restrict__ Wr, const float* __restrict__ br,
                       const float* __restrict__ Lrw, const float* __restrict__ Lrb,
                       const float* __restrict__ Wh, const float* __restrict__ bh,
                       const float* __restrict__ Lhw, const float* __restrict__ Lhb) {
    int t = threadIdx.x;
    if (t >= 48) return;
    int gate = t >> 4;
    int j = t & 15;
    const float *W, *b, *L, *Lb;
    if      (gate == 0) { W = Wz; b = bz; L = Lzw; Lb = Lzb; }
    else if (gate == 1) { W = Wr; b = br; L = Lrw; Lb = Lrb; }
    else                { W = Wh; b = bh; L = Lhw; Lb = Lhb; }
#pragma unroll
    for (int k = 0; k < 8; k++) {
        float m = 0.0f;
#pragma unroll
        for (int i = 0; i < 16; i++) m = fmaf(W[k * 16 + i], L[i * 16 + j], m);
        g_M[gate * 128 + k * 16 + j] = m;
    }
    float fb = Lb[j];
#pragma unroll
    for (int i = 0; i < 16; i++) fb = fmaf(b[i], L[i * 16 + j], fb);
    g_fb[gate * 16 + j] = fb;
}

// Unordered CSR slot allocation: per-block scan + one global atomicAdd.
__global__ void k_alloc(int N) {
    __shared__ int wsum[8];
    __shared__ int sbase;
    int i = blockIdx.x * 256 + threadIdx.x;
    int lane = threadIdx.x & 31;
    int wid  = threadIdx.x >> 5;
    int c = (i < N) ? g_cnt[i] : 0;
    int v = c;
#pragma unroll
    for (int d = 1; d < 32; d <<= 1) {
        int u = __shfl_up_sync(0xffffffffu, v, d);
        if (lane >= d) v += u;
    }
    if (lane == 31) wsum[wid] = v;
    __syncthreads();
    if (threadIdx.x < 8) {
        int w = wsum[threadIdx.x];
#pragma unroll
        for (int d = 1; d < 8; d <<= 1) {
            int u = __shfl_up_sync(0xffu, w, d, 8);
            if (threadIdx.x >= (unsigned)d) w += u;
        }
        wsum[threadIdx.x] = w;
        if (threadIdx.x == 7) sbase = atomicAdd(&g_total, w);
    }
    __syncthreads();
    int excl = v - c + (wid > 0 ? wsum[wid - 1] : 0) + sbase;
    if (i < N) g_off[i] = excl;
}

__global__ void k_scatter(const int* __restrict__ ei, int E) {
    int e = blockIdx.x * blockDim.x + threadIdx.x;
    if (e >= E) return;
    int d = ei[E + e];
    int p = atomicAdd(&g_pos[d], 1);
    g_csr[g_off[d] + p] = ei[e];
}

// Gather-based propagation of all 8 initial slices + self term.
__global__ void k_gather_init(const float* __restrict__ x, int N) {
    int i = blockIdx.x * blockDim.x + threadIdx.x;
    int n = i >> 3;
    int f = i & 7;
    if (n >= N) return;
    float dn = g_dinv[n];
    float ns = g_nself[n];
    const float4* xs = (const float4*)(x + (size_t)n * 64 + f * 8);
    float4 sa = xs[0], sb = xs[1];
    float a0 = ns * sa.x, a1 = ns * sa.y, a2 = ns * sa.z, a3 = ns * sa.w;
    float a4 = ns * sb.x, a5 = ns * sb.y, a6 = ns * sb.z, a7 = ns * sb.w;
    int beg = g_off[n], end = beg + g_cnt[n];
#pragma unroll 4
    for (int j = beg; j < end; j++) {
        int s = g_csr[j];
        float ne = dn * g_dinv[s];
        const float4* xp = (const float4*)(x + (size_t)s * 64 + f * 8);
        float4 u = xp[0], v = xp[1];
        a0 = fmaf(u.x, ne, a0); a1 = fmaf(u.y, ne, a1);
        a2 = fmaf(u.z, ne, a2); a3 = fmaf(u.w, ne, a3);
        a4 = fmaf(v.x, ne, a4); a5 = fmaf(v.y, ne, a5);
        a6 = fmaf(v.z, ne, a6); a7 = fmaf(v.w, ne, a7);
    }
    float* pr = g_Px + (size_t)n * ROWF + f;   // Px[n][t][f] = pr[t*8]
    pr[0]  = a0; pr[8]  = a1; pr[16] = a2; pr[24] = a3;
    pr[32] = a4; pr[40] = a5; pr[48] = a6; pr[56] = a7;
}

__device__ __forceinline__ float sigmoid_f(float x) {
    return __fdividef(1.0f, 1.0f + __expf(-x));
}
__device__ __forceinline__ float tanh_f(float x) {
    float e = __expf(-2.0f * x);
    return __fdividef(1.0f - e, 1.0f + e);
}

// One 16B weight load feeds BOTH nodes (8 FMAs per LDS.128).
#define ROWFMA2(BASE, ROW, VA, VB) do {                                   \
    float4 w_ = *(const float4*)((BASE) + (ROW) * 16 + q4);               \
    cA0 = fmaf((VA), w_.x, cA0); cA1 = fmaf((VA), w_.y, cA1);             \
    cA2 = fmaf((VA), w_.z, cA2); cA3 = fmaf((VA), w_.w, cA3);             \
    cB0 = fmaf((VB), w_.x, cB0); cB1 = fmaf((VB), w_.y, cB1);             \
    cB2 = fmaf((VB), w_.z, cB2); cB3 = fmaf((VB), w_.w, cB3); } while (0)

// Layer-1 folded: 8 input features through the 8x16 M matrix, two nodes at once
#define DOT8P2(BASE) do {                                                 \
    ROWFMA2(BASE, 0, qaA.x, qaB.x);                                       \
    ROWFMA2(BASE, 1, qaA.y, qaB.y);                                       \
    ROWFMA2(BASE, 2, qaA.z, qaB.z);                                       \
    ROWFMA2(BASE, 3, qaA.w, qaB.w);                                       \
    ROWFMA2(BASE, 4, qbA.x, qbB.x);                                       \
    ROWFMA2(BASE, 5, qbA.y, qbB.y);                                       \
    ROWFMA2(BASE, 6, qbA.z, qbB.z);                                       \
    ROWFMA2(BASE, 7, qbA.w, qbB.w); } while (0)

// Gather 16 per-unit values spread 4-per-lane across the 4-lane node group
#define BCAST16(P, S0, S1, S2, S3) do {                                   \
    P##0  = __shfl_sync(0xffffffffu, S0, 0, 4);                           \
    P##1  = __shfl_sync(0xffffffffu, S1, 0, 4);                           \
    P##2  = __shfl_sync(0xffffffffu, S2, 0, 4);                           \
    P##3  = __shfl_sync(0xffffffffu, S3, 0, 4);                           \
    P##4  = __shfl_sync(0xffffffffu, S0, 1, 4);                           \
    P##5  = __shfl_sync(0xffffffffu, S1, 1, 4);                           \
    P##6  = __shfl_sync(0xffffffffu, S2, 1, 4);                           \
    P##7  = __shfl_sync(0xffffffffu, S3, 1, 4);                           \
    P##8  = __shfl_sync(0xffffffffu, S0, 2, 4);                           \
    P##9  = __shfl_sync(0xffffffffu, S1, 2, 4);                           \
    P##10 = __shfl_sync(0xffffffffu, S2, 2, 4);                           \
    P##11 = __shfl_sync(0xffffffffu, S3, 2, 4);                           \
    P##12 = __shfl_sync(0xffffffffu, S0, 3, 4);                           \
    P##13 = __shfl_sync(0xffffffffu, S1, 3, 4);                           \
    P##14 = __shfl_sync(0xffffffffu, S2, 3, 4);                           \
    P##15 = __shfl_sync(0xffffffffu, S3, 3, 4); } while (0)

// 16 broadcast values (per node) times 16 rows of the H-portion matrix
#define DOT16H(BASE, PA, PB) do {                                         \
    ROWFMA2(BASE, 0,  PA##0,  PB##0);                                     \
    ROWFMA2(BASE, 1,  PA##1,  PB##1);                                     \
    ROWFMA2(BASE, 2,  PA##2,  PB##2);                                     \
    ROWFMA2(BASE, 3,  PA##3,  PB##3);                                     \
    ROWFMA2(BASE, 4,  PA##4,  PB##4);                                     \
    ROWFMA2(BASE, 5,  PA##5,  PB##5);                                     \
    ROWFMA2(BASE, 6,  PA##6,  PB##6);                                     \
    ROWFMA2(BASE, 7,  PA##7,  PB##7);                                     \
    ROWFMA2(BASE, 8,  PA##8,  PB##8);                                     \
    ROWFMA2(BASE, 9,  PA##9,  PB##9);                                     \
    ROWFMA2(BASE, 10, PA##10, PB##10);                                    \
    ROWFMA2(BASE, 11, PA##11, PB##11);                                    \
    ROWFMA2(BASE, 12, PA##12, PB##12);                                    \
    ROWFMA2(BASE, 13, PA##13, PB##13);                                    \
    ROWFMA2(BASE, 14, PA##14, PB##14);                                    \
    ROWFMA2(BASE, 15, PA##15, PB##15); } while (0)

// Per-node output projection + stores
#define EPILOGUE(AX0, AX1, AX2, AX3, NODE, VALID) do {                    \
    float r0 = fmaxf(AX0, 0.f), r1 = fmaxf(AX1, 0.f);                     \
    float r2 = fmaxf(AX2, 0.f), r3 = fmaxf(AX3, 0.f);                     \
    float o0 = OUTF(0), o1 = OUTF(1), o2 = OUTF(2), o3 = OUTF(3);         \
    float o4 = OUTF(4), o5 = OUTF(5), o6 = OUTF(6), o7 = OUTF(7);         \
    o0 += __shfl_xor_sync(0xffffffffu, o0, 1, 4);                         \
    o1 += __shfl_xor_sync(0xffffffffu, o1, 1, 4);                         \
    o2 += __shfl_xor_sync(0xffffffffu, o2, 1, 4);                         \
    o3 += __shfl_xor_sync(0xffffffffu, o3, 1, 4);                         \
    o4 += __shfl_xor_sync(0xffffffffu, o4, 1, 4);                         \
    o5 += __shfl_xor_sync(0xffffffffu, o5, 1, 4);                         \
    o6 += __shfl_xor_sync(0xffffffffu, o6, 1, 4);                         \
    o7 += __shfl_xor_sync(0xffffffffu, o7, 1, 4);                         \
    o0 += __shfl_xor_sync(0xffffffffu, o0, 2, 4);                         \
    o1 += __shfl_xor_sync(0xffffffffu, o1, 2, 4);                         \
    o2 += __shfl_xor_sync(0xffffffffu, o2, 2, 4);                         \
    o3 += __shfl_xor_sync(0xffffffffu, o3, 2, 4);                         \
    o4 += __shfl_xor_sync(0xffffffffu, o4, 2, 4);                         \
    o5 += __shfl_xor_sync(0xffffffffu, o5, 2, 4);                         \
    o6 += __shfl_xor_sync(0xffffffffu, o6, 2, 4);                         \
    o7 += __shfl_xor_sync(0xffffffffu, o7, 2, 4);                         \
    o0 += sbo[0]; o1 += sbo[1]; o2 += sbo[2]; o3 += sbo[3];               \
    o4 += sbo[4]; o5 += sbo[5]; o6 += sbo[6]; o7 += sbo[7];               \
    float wa, wb2;                                                        \
    if      (q == 0) { wa = o0; wb2 = o1; }                               \
    else if (q == 1) { wa = o2; wb2 = o3; }                               \
    else if (q == 2) { wa = o4; wb2 = o5; }                               \
    else             { wa = o6; wb2 = o7; }                               \
    if (VALID) {                                                          \
        int f = 2 * q;                                                    \
        float* op = out + (size_t)(NODE) * 32 + o;                        \
        op[f * 4]       = wa;                                             \
        op[(f + 1) * 4] = wb2;                                            \
        if (o < 3) {                                                      \
            float ns = g_nself[(NODE)];                                   \
            float* hbp = g_hbuf + (size_t)(NODE) * 8;                     \
            float* psp = g_Px + (size_t)(NODE) * ROWF + (8 + o) * 8;      \
            hbp[f]     = wa;                                              \
            hbp[f + 1] = wb2;                                             \
            psp[f]     = ns * wa;                                         \
            psp[f + 1] = ns * wb2;                                        \
        }                                                                 \
    }                                                                     \
} while (0)

// Fused 8-step GRU scan for one output iteration o.
// 4 lanes per node, TWO nodes per lane (block covers 64 nodes).
// gate = sigma(P@M + H@L_bot + fb).
// Prologue (gslot >= 0): gather-propagate h into slot gslot for THIS block's
// 64 nodes (2 threads/node, 4 features each). Reads g_hbuf written by the
// previous scan (kernel boundary); self term already stored in Px by that
// scan's epilogue. Then __syncthreads and run the GRU.
__global__ void __launch_bounds__(128)
k_scan(const float* __restrict__ att,
       const float* __restrict__ Lzw, const float* __restrict__ Lrw,
       const float* __restrict__ Lhw,
       const float* __restrict__ Wout, const float* __restrict__ bout,
       float* __restrict__ out, int N, int o, int gslot)
{
    __shared__ __align__(16) float sMz[128], sMr[128], sMh[128];
    __shared__ __align__(16) float sLz[256], sLr[256], sLh[256];   // L bottom halves
    __shared__ __align__(16) float sfbz[16], sfbr[16], sfbh[16];
    __shared__ __align__(16) float sWo[128], sbo[8], sp[8];

    int tid = threadIdx.x;
    if (tid < 128) {
        sMz[tid] = g_M[tid]; sMr[tid] = g_M[128 + tid]; sMh[tid] = g_M[256 + tid];
        sWo[tid] = Wout[tid];
    }
    for (int i = tid; i < 256; i += 128) {
        sLz[i] = Lzw[256 + i]; sLr[i] = Lrw[256 + i]; sLh[i] = Lhw[256 + i];
    }
    if (tid < 16) {
        sfbz[tid] = g_fb[tid]; sfbr[tid] = g_fb[16 + tid]; sfbh[tid] = g_fb[32 + tid];
    }
    if (tid < 8) {
        sbo[tid] = bout[tid];
        float v = att[tid];
        float m = v;
        m = fmaxf(m, __shfl_xor_sync(0xffu, m, 1, 8));
        m = fmaxf(m, __shfl_xor_sync(0xffu, m, 2, 8));
        m = fmaxf(m, __shfl_xor_sync(0xffu, m, 4, 8));
        float e = __expf(v - m);
        float s = e;
        s += __shfl_xor_sync(0xffu, s, 1, 8);
        s += __shfl_xor_sync(0xffu, s, 2, 8);
        s += __shfl_xor_sync(0xffu, s, 4, 8);
        sp[tid] = __fdividef(e, s);
    }

    // ---- fused gather prologue for this block's nodes ----
    if (gslot >= 0) {
        int ln = tid >> 1;                         // local node 0..63
        int ng = blockIdx.x * 64 + ln;
        int fh = (tid & 1) * 4;                    // feature half 0 or 4
        if (ng < N) {
            float dn = g_dinv[ng];
            float* pp = g_Px + (size_t)ng * ROWF + gslot * 8 + fh;
            float4 acc = *(float4*)pp;             // self term from prev epilogue
            int beg = g_off[ng], end = beg + g_cnt[ng];
#pragma unroll 4
            for (int j = beg; j < end; j++) {
                int s = g_csr[j];
                float ne = dn * g_dinv[s];
                float4 hv = *(const float4*)(g_hbuf + (size_t)s * 8 + fh);
                acc.x = fmaf(hv.x, ne, acc.x);
                acc.y = fmaf(hv.y, ne, acc.y);
                acc.z = fmaf(hv.z, ne, acc.z);
                acc.w = fmaf(hv.w, ne, acc.w);
            }
            *(float4*)pp = acc;
        }
    }
    __syncthreads();

    int g = tid >> 2;
    int nodeA = blockIdx.x * 64 + g;
    int nodeB = nodeA + 32;
    bool validA = (nodeA < N);
    bool validB = (nodeB < N);
    if (nodeA >= N) nodeA = N - 1;
    if (nodeB >= N) nodeB = N - 1;
    int q  = tid & 3;
    int q4 = q * 4;

    float HA0 = 0.f, HA1 = 0.f, HA2 = 0.f, HA3 = 0.f;
    float HB0 = 0.f, HB1 = 0.f, HB2 = 0.f, HB3 = 0.f;
    float AA0 = 0.f, AA1 = 0.f, AA2 = 0.f, AA3 = 0.f;
    float AB0 = 0.f, AB1 = 0.f, AB2 = 0.f, AB3 = 0.f;

    const float* prowA = g_Px + (size_t)nodeA * ROWF + o * 8;
    const float* prowB = g_Px + (size_t)nodeB * ROWF + o * 8;

#pragma unroll 1
    for (int t = 0; t < 8; t++) {
        float4 qaA = ((const float4*)(prowA + t * 8))[0];
        float4 qbA = ((const float4*)(prowA + t * 8))[1];
        float4 qaB = ((const float4*)(prowB + t * 8))[0];
        float4 qbB = ((const float4*)(prowB + t * 8))[1];

        float hbA0, hbA1, hbA2, hbA3, hbA4, hbA5, hbA6, hbA7,
              hbA8, hbA9, hbA10, hbA11, hbA12, hbA13, hbA14, hbA15;
        float hbB0, hbB1, hbB2, hbB3, hbB4, hbB5, hbB6, hbB7,
              hbB8, hbB9, hbB10, hbB11, hbB12, hbB13, hbB14, hbB15;
        BCAST16(hbA, HA0, HA1, HA2, HA3);
        BCAST16(hbB, HB0, HB1, HB2, HB3);

        float ZA0, ZA1, ZA2, ZA3, ZB0, ZB1, ZB2, ZB3;
        float RA0, RA1, RA2, RA3, RB0, RB1, RB2, RB3;
        float TA0, TA1, TA2, TA3, TB0, TB1, TB2, TB3;

        {   // ---- z gate ----
            float4 bv = *(const float4*)(sfbz + q4);
            float cA0 = bv.x, cA1 = bv.y, cA2 = bv.z, cA3 = bv.w;
            float cB0 = bv.x, cB1 = bv.y, cB2 = bv.z, cB3 = bv.w;
            DOT8P2(sMz);
            DOT16H(sLz, hbA, hbB);
            ZA0 = sigmoid_f(cA0); ZA1 = sigmoid_f(cA1); ZA2 = sigmoid_f(cA2); ZA3 = sigmoid_f(cA3);
            ZB0 = sigmoid_f(cB0); ZB1 = sigmoid_f(cB1); ZB2 = sigmoid_f(cB2); ZB3 = sigmoid_f(cB3);
        }
        {   // ---- r gate -> H*R ----
            float4 bv = *(const float4*)(sfbr + q4);
            float cA0 = bv.x, cA1 = bv.y, cA2 = bv.z, cA3 = bv.w;
            float cB0 = bv.x, cB1 = bv.y, cB2 = bv.z, cB3 = bv.w;
            DOT8P2(sMr);
            DOT16H(sLr, hbA, hbB);
            RA0 = HA0 * sigmoid_f(cA0); RA1 = HA1 * sigmoid_f(cA1);
            RA2 = HA2 * sigmoid_f(cA2); RA3 = HA3 * sigmoid_f(cA3);
            RB0 = HB0 * sigmoid_f(cB0); RB1 = HB1 * sigmoid_f(cB1);
            RB2 = HB2 * sigmoid_f(cB2); RB3 = HB3 * sigmoid_f(cB3);
        }
        {   // ---- h gate ----
            BCAST16(hbA, RA0, RA1, RA2, RA3);   // reuse hb regs for H*R broadcast
            BCAST16(hbB, RB0, RB1, RB2, RB3);
            float4 bv = *(const float4*)(sfbh + q4);
            float cA0 = bv.x, cA1 = bv.y, cA2 = bv.z, cA3 = bv.w;
            float cB0 = bv.x, cB1 = bv.y, cB2 = bv.z, cB3 = bv.w;
            DOT8P2(sMh);
            DOT16H(sLh, hbA, hbB);
            TA0 = tanh_f(cA0); TA1 = tanh_f(cA1); TA2 = tanh_f(cA2); TA3 = tanh_f(cA3);
            TB0 = tanh_f(cB0); TB1 = tanh_f(cB1); TB2 = tanh_f(cB2); TB3 = tanh_f(cB3);
        }

        float pt = sp[t];
        HA0 = ZA0 * HA0 + (1.0f - ZA0) * TA0;  AA0 = fmaf(pt, HA0, AA0);
        HA1 = ZA1 * HA1 + (1.0f - ZA1) * TA1;  AA1 = fmaf(pt, HA1, AA1);
        HA2 = ZA2 * HA2 + (1.0f - ZA2) * TA2;  AA2 = fmaf(pt, HA2, AA2);
        HA3 = ZA3 * HA3 + (1.0f - ZA3) * TA3;  AA3 = fmaf(pt, HA3, AA3);
        HB0 = ZB0 * HB0 + (1.0f - ZB0) * TB0;  AB0 = fmaf(pt, HB0, AB0);
        HB1 = ZB1 * HB1 + (1.0f - ZB1) * TB1;  AB1 = fmaf(pt, HB1, AB1);
        HB2 = ZB2 * HB2 + (1.0f - ZB2) * TB2;  AB2 = fmaf(pt, HB2, AB2);
        HB3 = ZB3 * HB3 + (1.0f - ZB3) * TB3;  AB3 = fmaf(pt, HB3, AB3);
    }

#define OUTF(F) (fmaf(r0, sWo[(q4 + 0) * 8 + (F)],                        \
                 fmaf(r1, sWo[(q4 + 1) * 8 + (F)],                        \
                 fmaf(r2, sWo[(q4 + 2) * 8 + (F)],                        \
                      r3 * sWo[(q4 + 3) * 8 + (F)]))))
    EPILOGUE(AA0, AA1, AA2, AA3, nodeA, validA);
    EPILOGUE(AB0, AB1, AB2, AB3, nodeB, validB);
#undef OUTF
}

// ---------------------------------------------------------------------------
extern "C" void kernel_launch(void* const* d_in, const int* in_sizes, int n_in,
                              void* d_out, int out_size)
{
    const float* x    = (const float*)d_in[0];
    const int*   ei   = (const int*)d_in[1];
    const float* att  = (const float*)d_in[2];
    const float* Wz   = (const float*)d_in[3];
    const float* bz   = (const float*)d_in[4];
    const float* Lzw  = (const float*)d_in[5];
    const float* Lzb  = (const float*)d_in[6];
    const float* Wr   = (const float*)d_in[7];
    const float* br   = (const float*)d_in[8];
    const float* Lrw  = (const float*)d_in[9];
    const float* Lrb  = (const float*)d_in[10];
    const float* Wh   = (const float*)d_in[11];
    const float* bh   = (const float*)d_in[12];
    const float* Lhw  = (const float*)d_in[13];
    const float* Lhb  = (const float*)d_in[14];
    const float* Wout = (const float*)d_in[15];
    const float* bout = (const float*)d_in[16];
    float* out = (float*)d_out;

    int N = in_sizes[0] / (FND * TIN);
    int E = in_sizes[1] / 2;
    if (N > NN) N = NN;   // static scratch capacity guard
    if (E > EE) E = EE;

    const int TB = 256;
    // ---- CSR build + weight fold (once per launch) ----
    k_zero_int<<<(N + TB - 1) / TB, TB>>>(N);
    k_cnt<<<(E + TB - 1) / TB, TB>>>(ei, E);
    k_norm<<<(N + TB - 1) / TB, TB>>>(N);
    k_alloc<<<(N + 255) / 256, 256>>>(N);
    k_scatter<<<(E + TB - 1) / TB, TB>>>(ei, E);
    k_fold<<<1, 64>>>(Wz, bz, Lzw, Lzb, Wr, br, Lrw, Lrb, Wh, bh, Lhw, Lhb);
    // ---- initial propagation (gather, no atomics) ----
    {
        long long tot = (long long)N * 8;
        k_gather_init<<<(int)((tot + TB - 1) / TB), TB>>>(x, N);
    }

    for (int o = 0; o < TOUTN; o++) {
        int gslot = (o == 0) ? -1 : (7 + o);   // gather h into newest slot in-kernel
        k_scan<<<(N + 63) / 64, 128>>>(att, Lzw, Lrw, Lhw, Wout, bout, out, N, o, gslot);
    }
}